// round 11
// baseline (speedup 1.0000x reference)
#include <cuda_runtime.h>
#include <math.h>

#define BB 16
#define AA 3
#define CC 80
#define HH 76
#define WW 76
#define TT 50
#define PLANE (HH*WW)            // 5776
#define NPLANES (BB*AA)          // 48 conf planes
#define NT (BB*TT)               // 800 targets
#define NTHREADS 512
#define GRID 148                 // one block per SM
#define TGT_BLOCKS 50            // blocks 0..49: 16 target warps each = 800
#define DEDUPE_BASE 132          // blocks 132..147: per-batch dedupe
#define QPP 1444                 // float4 quads per plane
#define QTOT (NPLANES*QPP)       // 69312 quads; 148*512=75776 threads
#define BATCH_BITWORDS ((AA*PLANE + 31)/32)   // 542 words = 2.2KB
#define NSLOT 32
#define SLOT_STRIDE 64           // 256B apart -> distinct L2 slices

__constant__ float c_anch[18] = {10.f,13.f,16.f,30.f,33.f,23.f,30.f,61.f,62.f,45.f,
                                 59.f,119.f,116.f,90.f,156.f,198.f,373.f,326.f};

__device__ float g_slot[NSLOT * SLOT_STRIDE];   // zero at load; reset by tail
__device__ int   g_done = 0;                    // completion counter

__device__ __forceinline__ float sigf(float z) {
    return __fdividef(1.f, 1.f + __expf(-z));
}
// BCE on logits: -log(sig(v)) = softplus(-v); -log1p(-sig(v)) = softplus(v)
__device__ __forceinline__ float softplus(float x) {
    return __logf(1.f + __expf(x));
}

__device__ __forceinline__ void anchor_match(float tw, float th, int& bi) {
    float best = -1e30f; bi = 0;
    #pragma unroll
    for (int k = 0; k < 9; k++) {
        float aw = c_anch[2 * k]     * (1.f / 608.f);
        float ah = c_anch[2 * k + 1] * (1.f / 608.f);
        float inter = fminf(tw, aw) * fminf(th, ah);
        float uni   = tw * th + aw * ah - inter;
        float iou   = __fdividef(inter, uni);
        if (iou > best) { best = iou; bi = k; }
    }
}

__global__ void __launch_bounds__(NTHREADS, 1)
fused_kernel(const float* __restrict__ in,
             const float* __restrict__ tgt,
             float* __restrict__ out) {
    __shared__ unsigned bm[BATCH_BITWORDS];  // dedupe blocks only
    __shared__ int s_islast;
    __shared__ int s_va;

    int tid = threadIdx.x;
    int w = tid >> 5, l = tid & 31;
    int bid = blockIdx.x;

    // ── issue conf load (1 float4 per thread, flat over all 48 planes) ──
    int g = bid * NTHREADS + tid;
    bool hasconf = (g < QTOT);
    float4 xv = make_float4(0.f, 0.f, 0.f, 0.f);
    if (hasconf) {
        int p = g / QPP;                 // plane 0..47
        int q = g - p * QPP;
        int b = p / AA, a = p - b * AA;
        xv = ((const float4*)(in + (size_t)(b * 255 + a * 85 + 4) * PLANE))[q];
    }

    // ── target prologue (blocks 0..49, one warp per target): issue gather ──
    bool is_tgtblk = (bid < TGT_BLOCKS);
    bool dog = false;
    float v0 = 0.f, v1 = 0.f, v2 = 0.f;
    float tx_t = 0.f, ty_t = 0.f, tw_t = 0.f, th_t = 0.f, scale = 0.f;
    int ci = 0;
    if (is_tgtblk) {
        int t = bid * 16 + w;            // 0..799
        const float* t5 = tgt + t * 5;
        float tc = t5[0], tx = t5[1], ty = t5[2], tw = t5[3], th = t5[4];
        int valid = ((tc + tx + ty + tw + th) != 0.f);
        int bi; anchor_match(tw, th, bi);
        dog = valid && (bi < AA);
        if (dog) {
            int a_n = bi;
            int gi = (int)(tx * (float)WW); gi = min(max(gi, 0), WW - 1);
            int gj = (int)(ty * (float)HH); gj = min(max(gj, 0), HH - 1);
            int pos = gj * WW + gi;
            float aw_s = c_anch[2 * a_n], ah_s = c_anch[2 * a_n + 1];
            tx_t = tx * (float)WW - (float)gi;
            ty_t = ty * (float)HH - (float)gj;
            tw_t = __logf(tw * 608.f / aw_s);
            th_t = __logf(th * 608.f / ah_s);
            scale = 2.f * ty * tw;       // faithful to reference quirk
            ci = (int)tc;
            const float* base = in + (size_t)((t / TT) * 255 + a_n * 85) * PLANE + pos;
            v0 = base[(size_t)l * PLANE];           // loads fly during conf math
            v1 = base[(size_t)(l + 32) * PLANE];
            if (l + 64 < 85) v2 = base[(size_t)(l + 64) * PLANE];
        }
    }

    // ── conf compute: 4-way common denominator, 5 MUFU / 4 elements ──
    float confsum = 0.f;
    if (hasconf) {
        float e0 = __expf(-xv.x), e1 = __expf(-xv.y);
        float e2 = __expf(-xv.z), e3 = __expf(-xv.w);
        float d0 = 1.f + e0, d1 = 1.f + e1, d2 = 1.f + e2, d3 = 1.f + e3;
        float s1 = d0 * d1, s2 = d2 * d3;
        float num = s2 * (d0 + d1) + s1 * (d2 + d3);
        confsum = __fdividef(num, s1 * s2);   // = sig(x)+sig(y)+sig(z)+sig(w)
    }
    for (int o = 16; o > 0; o >>= 1) confsum += __shfl_down_sync(0xffffffffu, confsum, o);
    float* slot = &g_slot[((bid + w) & (NSLOT - 1)) * SLOT_STRIDE];
    if (l == 0 && confsum != 0.f) atomicAdd(slot, confsum);

    // ── target epilogue: block num_truths + per-warp loss ──
    if (is_tgtblk) {
        if (tid == 0) s_va = 0;
        __syncthreads();
        {
            int va = 0;
            #pragma unroll
            for (int q = tid; q < NT; q += NTHREADS) {     // tid, tid+512
                const float* q5 = tgt + q * 5;
                va += ((q5[0] + q5[1] + q5[2] + q5[3] + q5[4]) != 0.f);
            }
            for (int o = 16; o > 0; o >>= 1) va += __shfl_down_sync(0xffffffffu, va, o);
            if (l == 0 && va) atomicAdd(&s_va, va);
        }
        __syncthreads();
        float inv_nt = __fdividef(1.f, fmaxf((float)s_va, 1.f));

        if (dog) {
            float acc_xy = 0.f, acc_cls = 0.f;
            if (l == 0)      acc_xy += scale * fabsf(sigf(v0) - tx_t);
            else if (l == 1) acc_xy += scale * fabsf(sigf(v0) - ty_t);
            else if (l == 2) acc_xy += scale * fabsf(v0 - tw_t);
            else if (l == 3) acc_xy += scale * fabsf(v0 - th_t);
            else if (l != 4) acc_cls += softplus((l - 5 == ci) ? -v0 : v0);
            acc_cls += softplus((l + 27 == ci) ? -v1 : v1);
            if (l + 64 < 85) acc_cls += softplus((l + 59 == ci) ? -v2 : v2);

            float acc = acc_cls + acc_xy * inv_nt;
            for (int o = 16; o > 0; o >>= 1)
                acc += __shfl_down_sync(0xffffffffu, acc, o);
            if (l == 0) atomicAdd(slot, acc);
        }
    }

    // ── per-batch dedupe on blocks 132..147 (little conf work there) ──
    if (bid >= DEDUPE_BASE) {
        int batch = bid - DEDUPE_BASE;
        if (tid < BATCH_BITWORDS) bm[tid] = 0u;
        if (tid + NTHREADS < BATCH_BITWORDS) bm[tid + NTHREADS] = 0u;
        __syncthreads();
        if (tid < TT) {
            const float* t5 = tgt + (batch * TT + tid) * 5;
            float tc = t5[0], tx = t5[1], ty = t5[2], tw = t5[3], th = t5[4];
            int valid = ((tc + tx + ty + tw + th) != 0.f);
            int bi; anchor_match(tw, th, bi);
            if (valid && bi < AA) {
                int gi = (int)(tx * (float)WW); gi = min(max(gi, 0), WW - 1);
                int gj = (int)(ty * (float)HH); gj = min(max(gj, 0), HH - 1);
                int cell = (bi * HH + gj) * WW + gi;
                atomicOr(&bm[cell >> 5], 1u << (cell & 31));
            }
        }
        __syncthreads();
        int un = 0;
        if (tid < BATCH_BITWORDS) un = __popc(bm[tid]);
        if (tid + NTHREADS < BATCH_BITWORDS) un += __popc(bm[tid + NTHREADS]);
        for (int o = 16; o > 0; o >>= 1) un += __shfl_down_sync(0xffffffffu, un, o);
        if (l == 0 && un) atomicAdd(slot, -(float)un);
    }

    // ── completion protocol ──
    __syncthreads();
    if (tid == 0) {
        __threadfence();
        int old = atomicAdd(&g_done, 1);
        s_islast = (old == GRID - 1);
    }
    __syncthreads();
    if (!s_islast) return;

    // ── tail (last block, warp 0): 32 loads + shfl sum + store ──
    if (tid < 32) {
        if (tid == 0) __threadfence();
        __syncwarp();
        float v = g_slot[tid * SLOT_STRIDE];
        for (int o = 16; o > 0; o >>= 1) v += __shfl_down_sync(0xffffffffu, v, o);
        if (tid == 0) out[0] = v;
        g_slot[tid * SLOT_STRIDE] = 0.f;     // reset for next replay
        if (tid == 0) g_done = 0;
    }
}

extern "C" void kernel_launch(void* const* d_in, const int* in_sizes, int n_in,
                              void* d_out, int out_size) {
    const float* in  = (const float*)d_in[0];   // [16, 255, 76, 76]
    const float* tgt = (const float*)d_in[1];   // [16, 250]
    float* out = (float*)d_out;
    fused_kernel<<<GRID, NTHREADS>>>(in, tgt, out);
}

// round 12
// speedup vs baseline: 1.0284x; 1.0284x over previous
#include <cuda_runtime.h>
#include <math.h>

#define BB 16
#define AA 3
#define CC 80
#define HH 76
#define WW 76
#define TT 50
#define PLANE (HH*WW)            // 5776
#define NPLANES (BB*AA)          // 48 conf planes
#define NT (BB*TT)               // 800 targets
#define NTHREADS 512
#define GRID 148                 // one block per SM
#define TGT_BLOCKS 50            // blocks 0..49: 16 target warps each = 800
#define DEDUPE_BASE 132          // blocks 132..147: per-batch dedupe
#define QPP 1444                 // float4 quads per plane
#define QTOT (NPLANES*QPP)       // 69312 quads; 148*512=75776 threads
#define BATCH_BITWORDS ((AA*PLANE + 31)/32)   // 542 words = 2.2KB
#define NSLOT 32
#define SLOT_STRIDE 64           // 256B apart -> distinct L2 slices

__constant__ float c_anch[18] = {10.f,13.f,16.f,30.f,33.f,23.f,30.f,61.f,62.f,45.f,
                                 59.f,119.f,116.f,90.f,156.f,198.f,373.f,326.f};

__device__ float g_slot[NSLOT * SLOT_STRIDE];   // zero at load; reset by finish

__device__ __forceinline__ float sigf(float z) {
    return __fdividef(1.f, 1.f + __expf(-z));
}
// BCE on logits: -log(sig(v)) = softplus(-v); -log1p(-sig(v)) = softplus(v)
__device__ __forceinline__ float softplus(float x) {
    return __logf(1.f + __expf(x));
}

__device__ __forceinline__ void anchor_match(float tw, float th, int& bi) {
    float best = -1e30f; bi = 0;
    #pragma unroll
    for (int k = 0; k < 9; k++) {
        float aw = c_anch[2 * k]     * (1.f / 608.f);
        float ah = c_anch[2 * k + 1] * (1.f / 608.f);
        float inter = fminf(tw, aw) * fminf(th, ah);
        float uni   = tw * th + aw * ah - inter;
        float iou   = __fdividef(inter, uni);
        if (iou > best) { best = iou; bi = k; }
    }
}

// ───────────── kernel 1: all heavy work, REDG into slots, exit ─────────────
__global__ void __launch_bounds__(NTHREADS, 1)
fused_kernel(const float* __restrict__ in,
             const float* __restrict__ tgt) {
    __shared__ unsigned bm[BATCH_BITWORDS];  // dedupe blocks only
    __shared__ int s_va;

    int tid = threadIdx.x;
    int w = tid >> 5, l = tid & 31;
    int bid = blockIdx.x;

    // conf load: 1 float4 per thread, flat over the 48 conf planes
    int g = bid * NTHREADS + tid;
    bool hasconf = (g < QTOT);
    float4 xv = make_float4(0.f, 0.f, 0.f, 0.f);
    if (hasconf) {
        int p = g / QPP;
        int q = g - p * QPP;
        int b = p / AA, a = p - b * AA;
        xv = ((const float4*)(in + (size_t)(b * 255 + a * 85 + 4) * PLANE))[q];
    }

    // target prologue (blocks 0..49, one warp per target): issue gather early
    bool is_tgtblk = (bid < TGT_BLOCKS);
    bool dog = false;
    float v0 = 0.f, v1 = 0.f, v2 = 0.f;
    float tx_t = 0.f, ty_t = 0.f, tw_t = 0.f, th_t = 0.f, scale = 0.f;
    int ci = 0;
    if (is_tgtblk) {
        int t = bid * 16 + w;            // 0..799
        const float* t5 = tgt + t * 5;
        float tc = t5[0], tx = t5[1], ty = t5[2], tw = t5[3], th = t5[4];
        int valid = ((tc + tx + ty + tw + th) != 0.f);
        int bi; anchor_match(tw, th, bi);
        dog = valid && (bi < AA);
        if (dog) {
            int a_n = bi;
            int gi = (int)(tx * (float)WW); gi = min(max(gi, 0), WW - 1);
            int gj = (int)(ty * (float)HH); gj = min(max(gj, 0), HH - 1);
            int pos = gj * WW + gi;
            float aw_s = c_anch[2 * a_n], ah_s = c_anch[2 * a_n + 1];
            tx_t = tx * (float)WW - (float)gi;
            ty_t = ty * (float)HH - (float)gj;
            tw_t = __logf(tw * 608.f / aw_s);
            th_t = __logf(th * 608.f / ah_s);
            scale = 2.f * ty * tw;       // faithful to reference quirk
            ci = (int)tc;
            const float* base = in + (size_t)((t / TT) * 255 + a_n * 85) * PLANE + pos;
            v0 = base[(size_t)l * PLANE];
            v1 = base[(size_t)(l + 32) * PLANE];
            if (l + 64 < 85) v2 = base[(size_t)(l + 64) * PLANE];
        }
    }

    // conf compute: 4-way common denominator, 5 MUFU / 4 elements
    float confsum = 0.f;
    if (hasconf) {
        float e0 = __expf(-xv.x), e1 = __expf(-xv.y);
        float e2 = __expf(-xv.z), e3 = __expf(-xv.w);
        float d0 = 1.f + e0, d1 = 1.f + e1, d2 = 1.f + e2, d3 = 1.f + e3;
        float s1 = d0 * d1, s2 = d2 * d3;
        float num = s2 * (d0 + d1) + s1 * (d2 + d3);
        confsum = __fdividef(num, s1 * s2);
    }
    for (int o = 16; o > 0; o >>= 1) confsum += __shfl_down_sync(0xffffffffu, confsum, o);
    float* slot = &g_slot[((bid + w) & (NSLOT - 1)) * SLOT_STRIDE];
    if (l == 0 && confsum != 0.f) atomicAdd(slot, confsum);

    // target epilogue: block num_truths + per-warp loss
    if (is_tgtblk) {
        if (tid == 0) s_va = 0;
        __syncthreads();
        {
            int va = 0;
            for (int q = tid; q < NT; q += NTHREADS) {
                const float* q5 = tgt + q * 5;
                va += ((q5[0] + q5[1] + q5[2] + q5[3] + q5[4]) != 0.f);
            }
            for (int o = 16; o > 0; o >>= 1) va += __shfl_down_sync(0xffffffffu, va, o);
            if (l == 0 && va) atomicAdd(&s_va, va);
        }
        __syncthreads();
        float inv_nt = __fdividef(1.f, fmaxf((float)s_va, 1.f));

        if (dog) {
            float acc_xy = 0.f, acc_cls = 0.f;
            if (l == 0)      acc_xy += scale * fabsf(sigf(v0) - tx_t);
            else if (l == 1) acc_xy += scale * fabsf(sigf(v0) - ty_t);
            else if (l == 2) acc_xy += scale * fabsf(v0 - tw_t);
            else if (l == 3) acc_xy += scale * fabsf(v0 - th_t);
            else if (l != 4) acc_cls += softplus((l - 5 == ci) ? -v0 : v0);
            acc_cls += softplus((l + 27 == ci) ? -v1 : v1);
            if (l + 64 < 85) acc_cls += softplus((l + 59 == ci) ? -v2 : v2);

            float acc = acc_cls + acc_xy * inv_nt;   // fold /num_truths per-warp
            for (int o = 16; o > 0; o >>= 1)
                acc += __shfl_down_sync(0xffffffffu, acc, o);
            if (l == 0) atomicAdd(slot, acc);
        }
    }

    // per-batch dedupe on blocks 132..147
    if (bid >= DEDUPE_BASE) {
        int batch = bid - DEDUPE_BASE;
        if (tid < BATCH_BITWORDS) bm[tid] = 0u;
        if (tid + NTHREADS < BATCH_BITWORDS) bm[tid + NTHREADS] = 0u;
        __syncthreads();
        if (tid < TT) {
            const float* t5 = tgt + (batch * TT + tid) * 5;
            float tc = t5[0], tx = t5[1], ty = t5[2], tw = t5[3], th = t5[4];
            int valid = ((tc + tx + ty + tw + th) != 0.f);
            int bi; anchor_match(tw, th, bi);
            if (valid && bi < AA) {
                int gi = (int)(tx * (float)WW); gi = min(max(gi, 0), WW - 1);
                int gj = (int)(ty * (float)HH); gj = min(max(gj, 0), HH - 1);
                int cell = (bi * HH + gj) * WW + gi;
                atomicOr(&bm[cell >> 5], 1u << (cell & 31));
            }
        }
        __syncthreads();
        int un = 0;
        if (tid < BATCH_BITWORDS) un = __popc(bm[tid]);
        if (tid + NTHREADS < BATCH_BITWORDS) un += __popc(bm[tid + NTHREADS]);
        for (int o = 16; o > 0; o >>= 1) un += __shfl_down_sync(0xffffffffu, un, o);
        if (l == 0 && un) atomicAdd(slot, -(float)un);
    }
    // no completion protocol: block exits; kernel completion IS the sync.
}

// ───────────── kernel 2: PDL finish — waits on kernel 1 in hardware ────────
__global__ void finish_kernel(float* __restrict__ out) {
    cudaGridDependencySynchronize();     // HW wait: kernel 1 fully done + visible
    int t = threadIdx.x;                  // 32 threads
    float v = g_slot[t * SLOT_STRIDE];
    for (int o = 16; o > 0; o >>= 1) v += __shfl_down_sync(0xffffffffu, v, o);
    if (t == 0) out[0] = v;
    g_slot[t * SLOT_STRIDE] = 0.f;        // reset for next graph replay
}

extern "C" void kernel_launch(void* const* d_in, const int* in_sizes, int n_in,
                              void* d_out, int out_size) {
    const float* in  = (const float*)d_in[0];   // [16, 255, 76, 76]
    const float* tgt = (const float*)d_in[1];   // [16, 250]
    float* out = (float*)d_out;

    fused_kernel<<<GRID, NTHREADS>>>(in, tgt);

    // finish_kernel launched with Programmatic Stream Serialization:
    // it may begin while fused_kernel runs; cudaGridDependencySynchronize()
    // inside provides the completion wait. Launch ramp overlaps kernel 1.
    cudaLaunchConfig_t cfg = {};
    cfg.gridDim = dim3(1, 1, 1);
    cfg.blockDim = dim3(32, 1, 1);
    cfg.dynamicSmemBytes = 0;
    cfg.stream = 0;
    cudaLaunchAttribute attrs[1];
    attrs[0].id = cudaLaunchAttributeProgrammaticStreamSerialization;
    attrs[0].val.programmaticStreamSerializationAllowed = 1;
    cfg.attrs = attrs;
    cfg.numAttrs = 1;
    cudaLaunchKernelEx(&cfg, finish_kernel, out);
}

// round 14
// speedup vs baseline: 1.0394x; 1.0108x over previous
#include <cuda_runtime.h>
#include <math.h>

#define BB 16
#define AA 3
#define CC 80
#define HH 76
#define WW 76
#define TT 50
#define PLANE (HH*WW)            // 5776
#define NPLANES (BB*AA)          // 48 conf planes
#define NT (BB*TT)               // 800 targets
#define CONF_BLOCKS (NPLANES*2)  // 96 (half-plane per block)
#define TGT_BLOCKS 50            // 16 warps each -> exactly 800 warps
#define DEDUPE_BASE (CONF_BLOCKS + TGT_BLOCKS)       // 146
#define DEDUPE_BLOCKS BB                              // 16, one per batch
#define GRID (DEDUPE_BASE + DEDUPE_BLOCKS)            // 162; occ=2 -> one wave
#define NTHREADS 512
#define HALFQ 722                // float4 per half-plane
#define BATCH_BITWORDS ((AA*PLANE + 31)/32)          // 542 words = 2.2KB

__constant__ float c_anch[18] = {10.f,13.f,16.f,30.f,33.f,23.f,30.f,61.f,62.f,45.f,
                                 59.f,119.f,116.f,90.f,156.f,198.f,373.f,326.f};

// fast sigmoid: MUFU.EX2 + MUFU.RCP  (rel err ~1e-6, tolerance 1e-3)
__device__ __forceinline__ float sigf(float z) {
    return __fdividef(1.f, 1.f + __expf(-z));
}
// BCE on logits: -log(sig(v)) = softplus(-v); -log1p(-sig(v)) = softplus(v)
__device__ __forceinline__ float softplus(float x) {
    return __logf(1.f + __expf(x));
}

__device__ __forceinline__ void anchor_match(float tw, float th, int& bi) {
    float best = -1e30f; bi = 0;
    #pragma unroll
    for (int k = 0; k < 9; k++) {
        float aw = c_anch[2 * k]     * (1.f / 608.f);
        float ah = c_anch[2 * k + 1] * (1.f / 608.f);
        float inter = fminf(tw, aw) * fminf(th, ah);
        float uni   = tw * th + aw * ah - inter;
        float iou   = __fdividef(inter, uni);
        if (iou > best) { best = iou; bi = k; }
    }
}

// ── node 1: reset the output accumulator (replays accumulate otherwise) ──
__global__ void zero_kernel(float* __restrict__ out) {
    out[0] = 0.f;
    cudaTriggerProgrammaticLaunchCompletion();
}

// ── node 2: all work; every warp REDGs its contribution into out[0] ──
__global__ void __launch_bounds__(NTHREADS, 2)
fused_kernel(const float* __restrict__ in,
             const float* __restrict__ tgt,
             float* __restrict__ out) {
    __shared__ unsigned bm[BATCH_BITWORDS];  // per-batch bitmap (dedupe blocks)
    __shared__ int s_va;

    int tid = threadIdx.x;
    int l = tid & 31;
    int bid = blockIdx.x;

    if (bid < CONF_BLOCKS) {
        // half-plane sigmoid reduction: 2 explicit loads, MLP=2
        int plane = bid >> 1, half = bid & 1;
        int b = plane / AA, a = plane - b * AA;
        const float4* p = (const float4*)(in + (size_t)(b * 255 + a * 85 + 4) * PLANE)
                        + half * HALFQ;
        float4 v0 = p[tid];                    // tid < 722 always
        float4 v1;
        bool has1 = (tid + NTHREADS) < HALFQ;  // tid < 210
        if (has1) v1 = p[tid + NTHREADS];

        cudaGridDependencySynchronize();       // zero_kernel done (hides under loads)

        float s = sigf(v0.x) + sigf(v0.y) + sigf(v0.z) + sigf(v0.w);
        if (has1) s += sigf(v1.x) + sigf(v1.y) + sigf(v1.z) + sigf(v1.w);
        for (int o = 16; o > 0; o >>= 1) s += __shfl_down_sync(0xffffffffu, s, o);
        if (l == 0) atomicAdd(out, s);         // RED.ADD.F32 into output
    } else if (bid < DEDUPE_BASE) {
        // target blocks: one warp per target; gather loads issued first
        int t = (bid - CONF_BLOCKS) * 16 + (tid >> 5);
        const float* t5 = tgt + t * 5;
        float tc = t5[0], tx = t5[1], ty = t5[2], tw = t5[3], th = t5[4];
        int valid = ((tc + tx + ty + tw + th) != 0.f);
        int bi; anchor_match(tw, th, bi);
        bool dog = valid && (bi < AA);

        float v0 = 0.f, v1 = 0.f, v2 = 0.f;
        float tx_t = 0.f, ty_t = 0.f, tw_t = 0.f, th_t = 0.f, scale = 0.f;
        int ci = 0;
        if (dog) {
            int a_n = bi;
            int gi = (int)(tx * (float)WW); gi = min(max(gi, 0), WW - 1);
            int gj = (int)(ty * (float)HH); gj = min(max(gj, 0), HH - 1);
            int pos = gj * WW + gi;
            float aw_s = c_anch[2 * a_n], ah_s = c_anch[2 * a_n + 1];
            tx_t = tx * (float)WW - (float)gi;
            ty_t = ty * (float)HH - (float)gj;
            tw_t = __logf(tw * 608.f / aw_s);
            th_t = __logf(th * 608.f / ah_s);
            scale = 2.f * ty * tw;            // faithful to reference quirk
            ci = (int)tc;
            const float* base = in + (size_t)((t / TT) * 255 + a_n * 85) * PLANE + pos;
            v0 = base[(size_t)l * PLANE];          // loads fly during scan below
            v1 = base[(size_t)(l + 32) * PLANE];
            if (l + 64 < 85) v2 = base[(size_t)(l + 64) * PLANE];
        }

        // block-local num_truths (independent of gather loads)
        if (tid == 0) s_va = 0;
        __syncthreads();
        {
            int va = 0;
            for (int q = tid; q < NT; q += NTHREADS) {
                const float* q5 = tgt + q * 5;
                va += ((q5[0] + q5[1] + q5[2] + q5[3] + q5[4]) != 0.f);
            }
            for (int o = 16; o > 0; o >>= 1) va += __shfl_down_sync(0xffffffffu, va, o);
            if (l == 0 && va) atomicAdd(&s_va, va);
        }
        __syncthreads();
        float inv_nt = __fdividef(1.f, fmaxf((float)s_va, 1.f));

        cudaGridDependencySynchronize();       // before first REDG to out

        if (dog) {
            float acc_xy = 0.f, acc_cls = 0.f;
            if (l == 0)      acc_xy += scale * fabsf(sigf(v0) - tx_t);
            else if (l == 1) acc_xy += scale * fabsf(sigf(v0) - ty_t);
            else if (l == 2) acc_xy += scale * fabsf(v0 - tw_t);
            else if (l == 3) acc_xy += scale * fabsf(v0 - th_t);
            else if (l != 4) acc_cls += softplus((l - 5 == ci) ? -v0 : v0);
            acc_cls += softplus((l + 27 == ci) ? -v1 : v1);
            if (l + 64 < 85) acc_cls += softplus((l + 59 == ci) ? -v2 : v2);

            float acc = acc_cls + acc_xy * inv_nt;   // fold /num_truths per-warp
            for (int o = 16; o > 0; o >>= 1)
                acc += __shfl_down_sync(0xffffffffu, acc, o);
            if (l == 0) atomicAdd(out, acc);
        }
    } else {
        // per-batch dedupe: 50 targets, 542-word bitmap
        int batch = bid - DEDUPE_BASE;
        if (tid < BATCH_BITWORDS) bm[tid] = 0u;
        if (tid + NTHREADS < BATCH_BITWORDS) bm[tid + NTHREADS] = 0u;
        __syncthreads();

        if (tid < TT) {
            const float* t5 = tgt + (batch * TT + tid) * 5;
            float tc = t5[0], tx = t5[1], ty = t5[2], tw = t5[3], th = t5[4];
            int valid = ((tc + tx + ty + tw + th) != 0.f);
            int bi; anchor_match(tw, th, bi);
            if (valid && bi < AA) {
                int gi = (int)(tx * (float)WW); gi = min(max(gi, 0), WW - 1);
                int gj = (int)(ty * (float)HH); gj = min(max(gj, 0), HH - 1);
                int cell = (bi * HH + gj) * WW + gi;   // batch-local cell
                atomicOr(&bm[cell >> 5], 1u << (cell & 31));
            }
        }
        __syncthreads();
        int un = 0;
        if (tid < BATCH_BITWORDS) un = __popc(bm[tid]);
        if (tid + NTHREADS < BATCH_BITWORDS) un += __popc(bm[tid + NTHREADS]);
        for (int o = 16; o > 0; o >>= 1) un += __shfl_down_sync(0xffffffffu, un, o);
        cudaGridDependencySynchronize();
        if (l == 0 && un) atomicAdd(out, -(float)un);
    }
    // no completion protocol, no tail: kernel completion is the sync.
}

extern "C" void kernel_launch(void* const* d_in, const int* in_sizes, int n_in,
                              void* d_out, int out_size) {
    const float* in  = (const float*)d_in[0];   // [16, 255, 76, 76]
    const float* tgt = (const float*)d_in[1];   // [16, 250]
    float* out = (float*)d_out;

    zero_kernel<<<1, 1>>>(out);

    // fused launched with Programmatic Stream Serialization: its ramp overlaps
    // zero_kernel; cudaGridDependencySynchronize() inside orders the atomics.
    cudaLaunchConfig_t cfg = {};
    cfg.gridDim = dim3(GRID, 1, 1);
    cfg.blockDim = dim3(NTHREADS, 1, 1);
    cfg.dynamicSmemBytes = 0;
    cfg.stream = 0;
    cudaLaunchAttribute attrs[1];
    attrs[0].id = cudaLaunchAttributeProgrammaticStreamSerialization;
    attrs[0].val.programmaticStreamSerializationAllowed = 1;
    cfg.attrs = attrs;
    cfg.numAttrs = 1;
    cudaLaunchKernelEx(&cfg, fused_kernel, in, tgt, out);
}